// round 10
// baseline (speedup 1.0000x reference)
#include <cuda_runtime.h>
#include <cuda_fp16.h>
#include <math.h>

#define N_NODES 20000
#define N_EDGES 320000
#define G_      64
#define RMAX    5.0f
#define TAB     512
#define NBLK    148         // one 1024-thread block per SM (GB300 has 152 SMs)
#define NTHR    1024
#define NWARPS  (NBLK * 32) // 4736
#define NSCB    20          // ceil(20000/1024)

// dynamic smem layout (bytes)
#define SM_TAB    0         // 512 rows x 64 half2 = 131072 B
#define SM_WINT   131072    // 2048 floats = 8192 B
#define SM_STAGE  139264    // 32 warps x 32 float4 = 16384 B (union: scan/hid)
#define SM_TOTAL  155648

// ---------------- device scratch (static; no allocation) ----------------
__device__ float4 g_pos4[N_NODES];
__device__ float  g_attrs[N_NODES * 10];
__device__ float  g_scalar[N_NODES * 32];
__device__ float  g_pred[N_NODES * 13];
__device__ int    g_deg[N_NODES];
__device__ int    g_rowptr[N_NODES + 1];
__device__ int    g_cursor[N_NODES];
__device__ int    g_part[NSCB];
__device__ int    g_wstart[NWARPS + 1];
__device__ int4   c_e[N_EDGES];             // {sender, half2(ux,uy), half2(uz,0), float tc}
__device__ float  g_rwtab[2 * TAB * 64];
__device__ __half2 g_tabh[2 * TAB * 64];
__device__ float  g_lacc[G_];
__device__ int    g_lcnt[G_];

// ---------------- grid barrier (all 148 blocks resident) ----------------
__device__ unsigned g_barArr = 0;
__device__ unsigned g_barGen = 0;

__device__ __forceinline__ void gridbar() {
    __syncthreads();
    if (threadIdx.x == 0) {
        __threadfence();
        unsigned gen = *(volatile unsigned*)&g_barGen;
        unsigned old = atomicAdd(&g_barArr, 1u);
        if (old == NBLK - 1) {
            g_barArr = 0;
            __threadfence();
            atomicAdd(&g_barGen, 1u);
        } else {
            while (*(volatile unsigned*)&g_barGen == gen) __nanosleep(64);
        }
        __threadfence();
    }
    __syncthreads();
}

// ---------------- fused layer phase ----------------
template <int LAYER>
__device__ __forceinline__ void layer_phase(char* dynsm,
                                            const float* __restrict__ W_mix,
                                            const float* __restrict__ W_prod,
                                            const float* __restrict__ W_sc,
                                            const float* __restrict__ W_ro_s,
                                            const float* __restrict__ W_ro_v,
                                            const float* __restrict__ eps,
                                            const int* __restrict__ batch) {
    float*  Wint  = (float*)(dynsm + SM_WINT);
    float4* stage = (float4*)(dynsm + SM_STAGE);
    const float2* smtab = (const float2*)(dynsm + SM_TAB);

    // copy this layer's table into smem (8192 float4)
    {
        const float4* src = (const float4*)(g_tabh + LAYER * TAB * 64);
        float4* dst = (float4*)(dynsm + SM_TAB);
        for (int i = threadIdx.x; i < (TAB * 64) / 4; i += NTHR)
            dst[i] = __ldg(&src[i]);
    }
    // interleaved W_mix: Wint[c*64 + d*2 + which]
    for (int i = threadIdx.x; i < 2048; i += NTHR) {
        int c = i >> 6, r = i & 63, d = r >> 1, which = r & 1;
        Wint[i] = W_mix[LAYER * 4096 + which * 1024 + c * 32 + d];
    }
    __syncthreads();

    int warp = threadIdx.x >> 5, lane = threadIdx.x & 31;
    int w = blockIdx.x * 32 + warp;
    int ns = g_wstart[w], ne = g_wstart[w + 1];
    float4* mystage = stage + warp * 32;
    float* stage_f = (float*)mystage;

    float wpa = __ldg(&W_prod[LAYER * 96 + lane]);
    float wpb = __ldg(&W_prod[LAYER * 96 + 32 + lane]);
    float wpc = __ldg(&W_prod[LAYER * 96 + 64 + lane]);
    float wsc[10];
    if (LAYER == 0) {
#pragma unroll
        for (int i = 0; i < 10; i++) wsc[i] = __ldg(&W_sc[i * 32 + lane]);
    }

    for (int n = ns; n < ne; n++) {
        float a0 = 0.0f, a1 = 0.0f, a2 = 0.0f, a3 = 0.0f;
        int beg = g_rowptr[n], end = g_rowptr[n + 1];
        if (beg < end) {
            int4 rN = __ldg(&c_e[beg]);
            float scN = __ldg(&g_scalar[rN.x * 32 + lane]);
            for (int p = beg; p < end; p++) {
                int4 rec = rN; float sc = scN;
                if (p + 1 < end) {
                    rN = __ldg(&c_e[p + 1]);
                    scN = __ldg(&g_scalar[rN.x * 32 + lane]);
                }
                float tc = __int_as_float(rec.w);
                int i0 = (int)tc;
                float fr = tc - (float)i0;
                float2 tv = smtab[i0 * 32 + lane];    // conflict-free LDS
                const __half2* hp = (const __half2*)&tv;
                float2 q0 = __half22float2(hp[0]);
                float2 q1 = __half22float2(hp[1]);
                float2 uxy = __half22float2(*(const __half2*)&rec.y);
                float uz = __low2float(*(const __half2*)&rec.z);
                float m0 = sc * fmaf(fr, q0.y, q0.x);
                float m1 = sc * fmaf(fr, q1.y, q1.x);
                a0 += m0;
                a1 = fmaf(m1, uxy.x, a1);
                a2 = fmaf(m1, uxy.y, a2);
                a3 = fmaf(m1, uz,    a3);
            }
        }

        // stage accumulators, mix via broadcast LDS
        mystage[lane] = make_float4(a0, a1, a2, a3);
        __syncwarp();
        float f0 = 0.0f, f1 = 0.0f, f2 = 0.0f, f3 = 0.0f;
#pragma unroll
        for (int c = 0; c < 32; c++) {
            float4 av = mystage[c];
            float2 wv = *(const float2*)&Wint[c * 64 + lane * 2];
            f0 = fmaf(av.x, wv.x, f0);
            f1 = fmaf(av.y, wv.y, f1);
            f2 = fmaf(av.z, wv.y, f2);
            f3 = fmaf(av.w, wv.y, f3);
        }

        float s0 = f0;
        float p = fmaf(fmaf(wpc, s0, wpb), s0, wpa);
        f0 *= p; f1 *= p; f2 *= p; f3 *= p;

        if (LAYER == 0) {
            float scv = 0.0f;
#pragma unroll
            for (int i = 0; i < 10; i++) scv = fmaf(g_attrs[n * 10 + i], wsc[i], scv);
            f0 += scv;
        }
        g_scalar[n * 32 + lane] = f0;

        __syncwarp();
        mystage[lane] = make_float4(f0, f1, f2, f3);
        __syncwarp();

        float e2 = 0.0f;
        if (lane < 13) {
            bool isv = lane >= 10;
            const float* wp = isv ? (W_ro_v + LAYER * 32)
                                  : (W_ro_s + LAYER * 320 + lane);
            int stride = isv ? 1 : 10;
            int comp = isv ? (lane - 9) : 0;
            float acc = 0.0f;
#pragma unroll 8
            for (int c = 0; c < 32; c++)
                acc = fmaf(stage_f[(c << 2) + comp], __ldg(wp + c * stride), acc);
            if (LAYER == 0) {
                g_pred[n * 13 + lane] = acc;
            } else {
                float d = g_pred[n * 13 + lane] + acc - eps[n * 13 + lane];
                e2 = d * d;
            }
        }
        if (LAYER == 1) {
#pragma unroll
            for (int o = 8; o; o >>= 1) e2 += __shfl_xor_sync(0xffffffffu, e2, o);
            if (lane == 0) {
                int g = batch[n];
                atomicAdd(&g_lacc[g], e2);
                atomicAdd(&g_lcnt[g], 1);
            }
        }
        __syncwarp();
    }
}

// ---------------- the mega-kernel ----------------
__global__ void __launch_bounds__(NTHR, 1)
k_mega(const float* __restrict__ pos,
       const float* __restrict__ attrs,
       const float* __restrict__ shifts,
       const float* __restrict__ eps,
       const float* __restrict__ alpha_bar,
       const float* __restrict__ W_embed,
       const float* __restrict__ W_r1,
       const float* __restrict__ W_r2,
       const float* __restrict__ W_mix,
       const float* __restrict__ W_sc,
       const float* __restrict__ W_prod,
       const float* __restrict__ W_ro_s,
       const float* __restrict__ W_ro_v,
       const int* __restrict__ ei,
       const int* __restrict__ batch,
       const int* __restrict__ t,
       float* __restrict__ out) {
    extern __shared__ char dynsm[];
    float* stagef = (float*)(dynsm + SM_STAGE);
    int tid = threadIdx.x;
    int bid = blockIdx.x;
    int gtid = bid * NTHR + tid;
    int lane = tid & 31, warp = tid >> 5;

    // ======== P0: node init + fp32 radial table ========
    if (gtid < N_NODES) {
        int n = gtid;
        if (n < G_) { g_lacc[n] = 0.0f; g_lcnt[n] = 0; }
        g_deg[n] = 0;
        int b = batch[n];
        int tt = t[b];
        float ab = alpha_bar[tt];
        float sa = sqrtf(ab), sb = sqrtf(1.0f - ab);
        g_pos4[n] = make_float4(sa * pos[n * 3 + 0] + sb * eps[n * 13 + 10],
                                sa * pos[n * 3 + 1] + sb * eps[n * 13 + 11],
                                sa * pos[n * 3 + 2] + sb * eps[n * 13 + 12], 0.0f);
        float an[10];
#pragma unroll
        for (int i = 0; i < 10; i++) {
            an[i] = sa * attrs[n * 10 + i] * 0.25f + sb * eps[n * 13 + i];
            g_attrs[n * 10 + i] = an[i];
        }
        float tf = (float)tt / 1000.0f;
#pragma unroll 4
        for (int c = 0; c < 32; c++) {
            float h = tf * W_embed[10 * 32 + c];
#pragma unroll
            for (int i = 0; i < 10; i++) h += an[i] * W_embed[i * 32 + c];
            g_scalar[n * 32 + c] = h;
        }
    }
    // radial table rows: block bid<64 handles rows [bid*16, bid*16+16)
    if (bid < (2 * TAB) / 16) {
        int sub = tid >> 6;     // 0..15
        int j = tid & 63;
        int row = bid * 16 + sub;
        int l = row / TAB;
        int i = row & (TAB - 1);
        float r = (float)i * (RMAX / (float)(TAB - 1));
        float rc = fmaxf(r, 1e-9f);
        if (j == 0) {
            const float PI_ = 3.14159265358979323846f;
            float th = PI_ * rc / RMAX;
            stagef[1024 + sub * 2 + 0] = sinf(th);
            stagef[1024 + sub * 2 + 1] = cosf(th);
        }
        __syncthreads();
        float s1 = stagef[1024 + sub * 2 + 0];
        float c2 = 2.0f * stagef[1024 + sub * 2 + 1];
        float xr = r / RMAX;
        float xr2 = xr * xr;
        float xr6 = xr2 * xr2 * xr2;
        float f = 1.0f - 28.0f * xr6 + 48.0f * xr6 * xr - 21.0f * xr6 * xr2;
        if (xr >= 1.0f) f = 0.0f;
        float g = 0.6324555320336759f * f / rc;   // sqrt(2/5) * cutoff / r
        float sp = 0.0f, sn = s1;
        float h = 0.0f;
#pragma unroll
        for (int nb = 0; nb < 8; nb++) {
            h = fmaf(g * sn, W_r1[l * 512 + nb * 64 + j], h);
            float nx = fmaf(c2, sn, -sp);
            sp = sn; sn = nx;
        }
        stagef[sub * 64 + j] = h / (1.0f + __expf(-h));   // silu
        __syncthreads();
        int col = ((j >> 1) << 2) | (j & 1);
        float acc = 0.0f;
#pragma unroll 8
        for (int h0 = 0; h0 < 64; h0++)
            acc += stagef[sub * 64 + h0] * W_r2[l * 8192 + h0 * 128 + col];
        g_rwtab[row * 64 + j] = acc;
    }
    gridbar();

    // ======== P1: edge degree count ========
    for (int e = gtid; e < N_EDGES; e += NBLK * NTHR) {
        int s = ei[e], rc = ei[N_EDGES + e];
        float4 pr = __ldg(&g_pos4[rc]);
        float4 ps = __ldg(&g_pos4[s]);
        float vx = pr.x - ps.x + shifts[e * 3 + 0];
        float vy = pr.y - ps.y + shifts[e * 3 + 1];
        float vz = pr.z - ps.z + shifts[e * 3 + 2];
        float r2 = vx * vx + vy * vy + vz * vz;
        if (r2 < RMAX * RMAX) atomicAdd(&g_deg[rc], 1);
    }
    gridbar();

    // ======== P2: block partial sums (bid<NSCB) || table pack (rest) ========
    if (bid < NSCB) {
        int* shi = (int*)stagef;
        int i = bid * NTHR + tid;
        shi[tid] = (i < N_NODES) ? g_deg[i] : 0;
        __syncthreads();
        for (int off = 512; off; off >>= 1) {
            if (tid < off) shi[tid] += shi[tid + off];
            __syncthreads();
        }
        if (tid == 0) g_part[bid] = shi[0];
    } else {
        int base = (bid - NSCB) * NTHR + tid;
        for (int idx = base; idx < 2 * TAB * 64; idx += (NBLK - NSCB) * NTHR) {
            int row = idx >> 6;
            int il = row & (TAB - 1);
            int j = idx & 63;
            float scale = (j & 1) ? 0.10825317547305482f : 0.0625f;  // sqrt3/16 : 1/16
            float a = g_rwtab[idx] * scale;
            float d = (il < TAB - 1) ? (g_rwtab[idx + 64] * scale - a) : 0.0f;
            g_tabh[idx] = __floats2half2_rn(a, d);
        }
    }
    gridbar();

    // ======== P3: rowptr (bid<NSCB) ========
    if (bid < NSCB) {
        int* shi = (int*)stagef;      // [0..31] warp totals, [32..63] part prefix
        int i = bid * NTHR + tid;
        int dv = (i < N_NODES) ? g_deg[i] : 0;
        int x = dv;
#pragma unroll
        for (int o = 1; o < 32; o <<= 1) {
            int u = __shfl_up_sync(0xffffffffu, x, o);
            if (lane >= o) x += u;
        }
        if (lane == 31) shi[warp] = x;
        __syncthreads();
        if (warp == 0) {            // scan warp totals -> exclusive
            int v = shi[lane];
            int y = v;
#pragma unroll
            for (int o = 1; o < 32; o <<= 1) {
                int u = __shfl_up_sync(0xffffffffu, y, o);
                if (lane >= o) y += u;
            }
            shi[lane] = y - v;
        }
        if (warp == 1) {            // scan NSCB partials -> exclusive + total
            int v = (lane < NSCB) ? g_part[lane] : 0;
            int y = v;
#pragma unroll
            for (int o = 1; o < 32; o <<= 1) {
                int u = __shfl_up_sync(0xffffffffu, y, o);
                if (lane >= o) y += u;
            }
            shi[32 + lane] = y - v;
            if (lane == 31) shi[32 + 31] = y;   // total (lanes>=NSCB add 0)
        }
        __syncthreads();
        if (i < N_NODES) {
            int excl = x - dv + shi[warp] + shi[32 + bid];
            g_rowptr[i] = excl;
            g_cursor[i] = excl;
        }
        if (bid == 0 && tid == 0) g_rowptr[N_NODES] = shi[32 + 31];
    }
    gridbar();

    // ======== P4: balanced warp partition + CSR fill (recompute geometry) ========
    if (gtid <= NWARPS) {
        int tot = g_rowptr[N_NODES];
        int F = tot + 16 * N_NODES;
        int target = (int)(((long long)gtid * F) / NWARPS);
        int lo = 0, hi = N_NODES;
        while (lo < hi) {
            int mid = (lo + hi) >> 1;
            int key = g_rowptr[mid] + 16 * mid;
            if (key >= target) hi = mid; else lo = mid + 1;
        }
        g_wstart[gtid] = lo;
    }
    for (int e = gtid; e < N_EDGES; e += NBLK * NTHR) {
        int s = ei[e], rc = ei[N_EDGES + e];
        float4 pr = __ldg(&g_pos4[rc]);
        float4 ps = __ldg(&g_pos4[s]);
        float vx = pr.x - ps.x + shifts[e * 3 + 0];
        float vy = pr.y - ps.y + shifts[e * 3 + 1];
        float vz = pr.z - ps.z + shifts[e * 3 + 2];
        float r = sqrtf(vx * vx + vy * vy + vz * vz + 1e-12f);
        if (r >= RMAX) continue;
        int p = atomicAdd(&g_cursor[rc], 1);
        float inv = 1.0f / r;
        float tc = r * ((float)(TAB - 1) / RMAX);
        __half2 hxy = __floats2half2_rn(vx * inv, vy * inv);
        __half2 hz  = __floats2half2_rn(vz * inv, 0.0f);
        int4 rec;
        rec.x = s;
        rec.y = *(const int*)&hxy;
        rec.z = *(const int*)&hz;
        rec.w = __float_as_int(tc);
        c_e[p] = rec;
    }
    gridbar();

    // ======== P5/P6: layers ========
    layer_phase<0>(dynsm, W_mix, W_prod, W_sc, W_ro_s, W_ro_v, eps, batch);
    gridbar();
    layer_phase<1>(dynsm, W_mix, W_prod, W_sc, W_ro_s, W_ro_v, eps, batch);
    gridbar();

    // ======== P7: final output ========
    if (bid == 0 && tid < G_) {
        float nn = fmaxf((float)g_lcnt[tid], 1.0f);
        out[tid] = 0.5f * g_lacc[tid] / (nn * 13.0f);
    }
}

// ---------------- launcher ----------------
extern "C" void kernel_launch(void* const* d_in, const int* in_sizes, int n_in,
                              void* d_out, int out_size) {
    (void)in_sizes; (void)n_in; (void)out_size;
    (void)cudaFuncSetAttribute(k_mega, cudaFuncAttributeMaxDynamicSharedMemorySize, SM_TOTAL);
    k_mega<<<NBLK, NTHR, SM_TOTAL>>>(
        (const float*)d_in[0],  (const float*)d_in[1],  (const float*)d_in[2],
        (const float*)d_in[3],  (const float*)d_in[4],  (const float*)d_in[5],
        (const float*)d_in[6],  (const float*)d_in[7],  (const float*)d_in[8],
        (const float*)d_in[9],  (const float*)d_in[10], (const float*)d_in[11],
        (const float*)d_in[12], (const int*)d_in[13],   (const int*)d_in[14],
        (const int*)d_in[15],   (float*)d_out);
}

// round 11
// speedup vs baseline: 1.3332x; 1.3332x over previous
#include <cuda_runtime.h>
#include <cuda_fp16.h>
#include <math.h>

#define N_NODES 20000
#define N_EDGES 320000
#define G_      64
#define RMAX    5.0f
#define TAB     512
#define NBLK    592         // 148 SMs x 4 blocks guaranteed resident (64 regs)
#define NTHR    256
#define NWARPS  (NBLK * 8)  // 4736
#define NSCB    79          // ceil(20000/256)

// ---------------- device scratch (static; no allocation) ----------------
__device__ float4 g_pos4[N_NODES];
__device__ float  g_attrs[N_NODES * 10];
__device__ float  g_scalar[N_NODES * 32];
__device__ float  g_pred[N_NODES * 13];
__device__ float4 g_vt[N_EDGES];            // (ux,uy,uz,tc); tc>=TAB-1 => inactive
__device__ int    g_deg[N_NODES];
__device__ int    g_rowptr[N_NODES + 1];
__device__ int    g_cursor[N_NODES];
__device__ int    g_part[NSCB];
__device__ int    g_wstart[NWARPS + 1];
__device__ int4   c_e[N_EDGES];             // {sender, h2(ux,uy), h2(uz,0), f32 tc}
__device__ float  g_rwtab[2 * TAB * 64];
__device__ __half2 g_tabh[2 * TAB * 64];
__device__ float  g_lacc[G_];
__device__ int    g_lcnt[G_];

// ---------------- grid barrier (all blocks resident) ----------------
__device__ unsigned g_barArr = 0;
__device__ unsigned g_barGen = 0;

__device__ __forceinline__ void gridbar() {
    __syncthreads();
    if (threadIdx.x == 0) {
        __threadfence();
        unsigned gen = *(volatile unsigned*)&g_barGen;
        unsigned old = atomicAdd(&g_barArr, 1u);
        if (old == NBLK - 1) {
            g_barArr = 0;
            __threadfence();
            atomicAdd(&g_barGen, 1u);
        } else {
            while (*(volatile unsigned*)&g_barGen == gen) __nanosleep(64);
        }
        __threadfence();
    }
    __syncthreads();
}

// ---------------- per-edge accumulate ----------------
__device__ __forceinline__ void edge_acc(int4 rec, float sc, float2 tv,
                                         float& a0, float& a1, float& a2, float& a3) {
    float tc = __int_as_float(rec.w);
    int i0 = (int)tc;
    float fr = tc - (float)i0;
    const __half2* hp = (const __half2*)&tv;
    float2 q0 = __half22float2(hp[0]);
    float2 q1 = __half22float2(hp[1]);
    float2 uxy = __half22float2(*(const __half2*)&rec.y);
    float uz = __low2float(*(const __half2*)&rec.z);
    float m0 = sc * fmaf(fr, q0.y, q0.x);
    float m1 = sc * fmaf(fr, q1.y, q1.x);
    a0 += m0;
    a1 = fmaf(m1, uxy.x, a1);
    a2 = fmaf(m1, uxy.y, a2);
    a3 = fmaf(m1, uz,    a3);
}

// ---------------- fused layer phase ----------------
template <int LAYER>
__device__ __forceinline__ void layer_phase(float* Wint, float4* stage,
                                            const float* __restrict__ W_mix,
                                            const float* __restrict__ W_prod,
                                            const float* __restrict__ W_sc,
                                            const float* __restrict__ W_ro_s,
                                            const float* __restrict__ W_ro_v,
                                            const float* __restrict__ eps,
                                            const int* __restrict__ batch) {
    // interleaved W_mix: Wint[c*64 + d*2 + which]
    for (int i = threadIdx.x; i < 2048; i += NTHR) {
        int c = i >> 6, r = i & 63, d = r >> 1, which = r & 1;
        Wint[i] = W_mix[LAYER * 4096 + which * 1024 + c * 32 + d];
    }
    __syncthreads();

    int warp = threadIdx.x >> 5, lane = threadIdx.x & 31;
    int w = blockIdx.x * 8 + warp;
    int ns = g_wstart[w], ne = g_wstart[w + 1];
    const float2* tab = (const float2*)(g_tabh + LAYER * TAB * 64);
    float4* mystage = stage + warp * 32;
    float* stage_f = (float*)mystage;

    float wpa = __ldg(&W_prod[LAYER * 96 + lane]);
    float wpb = __ldg(&W_prod[LAYER * 96 + 32 + lane]);
    float wpc = __ldg(&W_prod[LAYER * 96 + 64 + lane]);
    float wsc[10];
    if (LAYER == 0) {
#pragma unroll
        for (int i = 0; i < 10; i++) wsc[i] = __ldg(&W_sc[i * 32 + lane]);
    }

    for (int n = ns; n < ne; n++) {
        float a0 = 0.0f, a1 = 0.0f, a2 = 0.0f, a3 = 0.0f;
        int beg = g_rowptr[n], end = g_rowptr[n + 1];
        int p = beg;
        // 4-wide batched loads: MLP ~4 on the random gathers
        for (; p + 4 <= end; p += 4) {
            int4 r0 = __ldg(&c_e[p + 0]);
            int4 r1 = __ldg(&c_e[p + 1]);
            int4 r2 = __ldg(&c_e[p + 2]);
            int4 r3 = __ldg(&c_e[p + 3]);
            float s0 = __ldg(&g_scalar[r0.x * 32 + lane]);
            float s1 = __ldg(&g_scalar[r1.x * 32 + lane]);
            float s2 = __ldg(&g_scalar[r2.x * 32 + lane]);
            float s3 = __ldg(&g_scalar[r3.x * 32 + lane]);
            float2 t0 = __ldg(tab + ((int)__int_as_float(r0.w)) * 32 + lane);
            float2 t1 = __ldg(tab + ((int)__int_as_float(r1.w)) * 32 + lane);
            float2 t2 = __ldg(tab + ((int)__int_as_float(r2.w)) * 32 + lane);
            float2 t3 = __ldg(tab + ((int)__int_as_float(r3.w)) * 32 + lane);
            edge_acc(r0, s0, t0, a0, a1, a2, a3);
            edge_acc(r1, s1, t1, a0, a1, a2, a3);
            edge_acc(r2, s2, t2, a0, a1, a2, a3);
            edge_acc(r3, s3, t3, a0, a1, a2, a3);
        }
        for (; p < end; p++) {
            int4 r0 = __ldg(&c_e[p]);
            float s0 = __ldg(&g_scalar[r0.x * 32 + lane]);
            float2 t0 = __ldg(tab + ((int)__int_as_float(r0.w)) * 32 + lane);
            edge_acc(r0, s0, t0, a0, a1, a2, a3);
        }

        // stage accumulators, mix via broadcast LDS
        mystage[lane] = make_float4(a0, a1, a2, a3);
        __syncwarp();
        float f0 = 0.0f, f1 = 0.0f, f2 = 0.0f, f3 = 0.0f;
#pragma unroll
        for (int c = 0; c < 32; c++) {
            float4 av = mystage[c];
            float2 wv = *(const float2*)&Wint[c * 64 + lane * 2];
            f0 = fmaf(av.x, wv.x, f0);
            f1 = fmaf(av.y, wv.y, f1);
            f2 = fmaf(av.z, wv.y, f2);
            f3 = fmaf(av.w, wv.y, f3);
        }

        float s0 = f0;
        float p2 = fmaf(fmaf(wpc, s0, wpb), s0, wpa);
        f0 *= p2; f1 *= p2; f2 *= p2; f3 *= p2;

        if (LAYER == 0) {
            float scv = 0.0f;
#pragma unroll
            for (int i = 0; i < 10; i++) scv = fmaf(g_attrs[n * 10 + i], wsc[i], scv);
            f0 += scv;
        }
        g_scalar[n * 32 + lane] = f0;

        __syncwarp();
        mystage[lane] = make_float4(f0, f1, f2, f3);
        __syncwarp();

        float e2 = 0.0f;
        if (lane < 13) {
            bool isv = lane >= 10;
            const float* wp = isv ? (W_ro_v + LAYER * 32)
                                  : (W_ro_s + LAYER * 320 + lane);
            int stride = isv ? 1 : 10;
            int comp = isv ? (lane - 9) : 0;
            float acc = 0.0f;
#pragma unroll 8
            for (int c = 0; c < 32; c++)
                acc = fmaf(stage_f[(c << 2) + comp], __ldg(wp + c * stride), acc);
            if (LAYER == 0) {
                g_pred[n * 13 + lane] = acc;
            } else {
                float d = g_pred[n * 13 + lane] + acc - eps[n * 13 + lane];
                e2 = d * d;
            }
        }
        if (LAYER == 1) {
#pragma unroll
            for (int o = 8; o; o >>= 1) e2 += __shfl_xor_sync(0xffffffffu, e2, o);
            if (lane == 0) {
                int g = batch[n];
                atomicAdd(&g_lacc[g], e2);
                atomicAdd(&g_lcnt[g], 1);
            }
        }
        __syncwarp();
    }
}

// ---------------- the mega-kernel ----------------
__global__ void __launch_bounds__(NTHR, 4)
k_mega(const float* __restrict__ pos,
       const float* __restrict__ attrs,
       const float* __restrict__ shifts,
       const float* __restrict__ eps,
       const float* __restrict__ alpha_bar,
       const float* __restrict__ W_embed,
       const float* __restrict__ W_r1,
       const float* __restrict__ W_r2,
       const float* __restrict__ W_mix,
       const float* __restrict__ W_sc,
       const float* __restrict__ W_prod,
       const float* __restrict__ W_ro_s,
       const float* __restrict__ W_ro_v,
       const int* __restrict__ ei,
       const int* __restrict__ batch,
       const int* __restrict__ t,
       float* __restrict__ out) {
    __shared__ float smu[2048];        // union: table hid+sincos / scan / Wint
    __shared__ float4 stage[8 * 32];   // per-warp staging (layer phases)
    int tid = threadIdx.x;
    int bid = blockIdx.x;
    int gtid = bid * NTHR + tid;

    // ======== P0: node init + fp32 radial table ========
    if (gtid < N_NODES) {
        int n = gtid;
        if (n < G_) { g_lacc[n] = 0.0f; g_lcnt[n] = 0; }
        g_deg[n] = 0;
        int b = batch[n];
        int tt = t[b];
        float ab = alpha_bar[tt];
        float sa = sqrtf(ab), sb = sqrtf(1.0f - ab);
        g_pos4[n] = make_float4(sa * pos[n * 3 + 0] + sb * eps[n * 13 + 10],
                                sa * pos[n * 3 + 1] + sb * eps[n * 13 + 11],
                                sa * pos[n * 3 + 2] + sb * eps[n * 13 + 12], 0.0f);
        float an[10];
#pragma unroll
        for (int i = 0; i < 10; i++) {
            an[i] = sa * attrs[n * 10 + i] * 0.25f + sb * eps[n * 13 + i];
            g_attrs[n * 10 + i] = an[i];
        }
        float tf = (float)tt / 1000.0f;
#pragma unroll 4
        for (int c = 0; c < 32; c++) {
            float h = tf * W_embed[10 * 32 + c];
#pragma unroll
            for (int i = 0; i < 10; i++) h += an[i] * W_embed[i * 32 + c];
            g_scalar[n * 32 + c] = h;
        }
    }
    // radial table: 4 rows per block; sin(n*th) via Chebyshev recurrence
    {
        int sub = tid >> 6;
        int j = tid & 63;
        for (int chunk = bid; chunk < (2 * TAB) / 4; chunk += NBLK) {
            __syncthreads();
            int row = chunk * 4 + sub;
            int l = row / TAB;
            int i = row & (TAB - 1);
            float r = (float)i * (RMAX / (float)(TAB - 1));
            float rc = fmaxf(r, 1e-9f);
            if (j == 0) {
                const float PI_ = 3.14159265358979323846f;
                float th = PI_ * rc / RMAX;
                smu[1024 + sub * 2 + 0] = sinf(th);
                smu[1024 + sub * 2 + 1] = cosf(th);
            }
            __syncthreads();
            float s1 = smu[1024 + sub * 2 + 0];
            float c2 = 2.0f * smu[1024 + sub * 2 + 1];
            float xr = r / RMAX;
            float xr2 = xr * xr;
            float xr6 = xr2 * xr2 * xr2;
            float f = 1.0f - 28.0f * xr6 + 48.0f * xr6 * xr - 21.0f * xr6 * xr2;
            if (xr >= 1.0f) f = 0.0f;
            float g = 0.6324555320336759f * f / rc;
            float sp = 0.0f, sn = s1;
            float h = 0.0f;
#pragma unroll
            for (int nb = 0; nb < 8; nb++) {
                h = fmaf(g * sn, W_r1[l * 512 + nb * 64 + j], h);
                float nx = fmaf(c2, sn, -sp);
                sp = sn; sn = nx;
            }
            smu[sub * 64 + j] = h / (1.0f + __expf(-h));
            __syncthreads();
            int col = ((j >> 1) << 2) | (j & 1);
            float acc = 0.0f;
#pragma unroll 8
            for (int h0 = 0; h0 < 64; h0++)
                acc += smu[sub * 64 + h0] * W_r2[l * 8192 + h0 * 128 + col];
            g_rwtab[row * 64 + j] = acc;
        }
    }
    gridbar();

    // ======== P1: edge geometry (store g_vt) + degree ========
    for (int e = gtid; e < N_EDGES; e += NBLK * NTHR) {
        int s = ei[e], rc = ei[N_EDGES + e];
        float4 pr = __ldg(&g_pos4[rc]);
        float4 ps = __ldg(&g_pos4[s]);
        float vx = pr.x - ps.x + shifts[e * 3 + 0];
        float vy = pr.y - ps.y + shifts[e * 3 + 1];
        float vz = pr.z - ps.z + shifts[e * 3 + 2];
        float r = sqrtf(vx * vx + vy * vy + vz * vz + 1e-12f);
        float inv = 1.0f / r;
        float tc = r * ((float)(TAB - 1) / RMAX);   // >= TAB-1 iff r >= RMAX
        g_vt[e] = make_float4(vx * inv, vy * inv, vz * inv, tc);
        if (r < RMAX) atomicAdd(&g_deg[rc], 1);
    }
    gridbar();

    // ======== P2: scan partials (blocks < NSCB) || table pack (rest) ========
    if (bid < NSCB) {
        int* shi = (int*)smu;
        int i = bid * 256 + tid;
        shi[tid] = (i < N_NODES) ? g_deg[i] : 0;
        __syncthreads();
        for (int off = 128; off; off >>= 1) {
            if (tid < off) shi[tid] += shi[tid + off];
            __syncthreads();
        }
        if (tid == 0) g_part[bid] = shi[0];
    } else {
        int base = (bid - NSCB) * NTHR + tid;
        for (int idx = base; idx < 2 * TAB * 64; idx += (NBLK - NSCB) * NTHR) {
            int row = idx >> 6;
            int il = row & (TAB - 1);
            int j = idx & 63;
            float scale = (j & 1) ? 0.10825317547305482f : 0.0625f;  // sqrt3/16 : 1/16
            float a = g_rwtab[idx] * scale;
            float d = (il < TAB - 1) ? (g_rwtab[idx + 64] * scale - a) : 0.0f;
            g_tabh[idx] = __floats2half2_rn(a, d);
        }
    }
    gridbar();

    // ======== P3: per-chunk offsets + local scan (blocks < NSCB) ========
    if (bid < NSCB) {
        int* shi = (int*)smu;
        int lane = tid & 31;
        int v = (tid < NSCB) ? g_part[tid] : 0;
        int below = (tid < bid) ? v : 0;
#pragma unroll
        for (int o = 16; o; o >>= 1) below += __shfl_xor_sync(0xffffffffu, below, o);
        __shared__ int s_off[8], s_tot[8];
        int w = tid >> 5;
        if (lane == 0) s_off[w] = below;
        int totp = v;
#pragma unroll
        for (int o = 16; o; o >>= 1) totp += __shfl_xor_sync(0xffffffffu, totp, o);
        if (lane == 0) s_tot[w] = totp;
        __syncthreads();
        int blkoff = 0, total = 0;
#pragma unroll
        for (int q = 0; q < 8; q++) { blkoff += s_off[q]; total += s_tot[q]; }
        int i = bid * 256 + tid;
        int dv = (i < N_NODES) ? g_deg[i] : 0;
        shi[tid] = dv;
        __syncthreads();
        for (int off = 1; off < 256; off <<= 1) {
            int u = (tid >= off) ? shi[tid - off] : 0;
            __syncthreads();
            shi[tid] += u;
            __syncthreads();
        }
        if (i < N_NODES) {
            int excl = shi[tid] - dv + blkoff;
            g_rowptr[i] = excl;
            g_cursor[i] = excl;
        }
        if (bid == NSCB - 1 && tid == 0) g_rowptr[N_NODES] = total;
    }
    gridbar();

    // ======== P4: balanced warp partition + CSR fill ========
    if (gtid <= NWARPS) {
        int tot = g_rowptr[N_NODES];
        int F = tot + 16 * N_NODES;
        int target = (int)(((long long)gtid * F) / NWARPS);
        int lo = 0, hi = N_NODES;
        while (lo < hi) {
            int mid = (lo + hi) >> 1;
            int key = g_rowptr[mid] + 16 * mid;
            if (key >= target) hi = mid; else lo = mid + 1;
        }
        g_wstart[gtid] = lo;
    }
    for (int e = gtid; e < N_EDGES; e += NBLK * NTHR) {
        float4 v = g_vt[e];
        if (v.w >= (float)(TAB - 1)) continue;
        int rc = ei[N_EDGES + e];
        int p = atomicAdd(&g_cursor[rc], 1);
        __half2 hxy = __floats2half2_rn(v.x, v.y);
        __half2 hz  = __floats2half2_rn(v.z, 0.0f);
        int4 rec;
        rec.x = ei[e];
        rec.y = *(const int*)&hxy;
        rec.z = *(const int*)&hz;
        rec.w = __float_as_int(v.w);
        c_e[p] = rec;
    }
    gridbar();

    // ======== P5/P6: layers ========
    layer_phase<0>(smu, stage, W_mix, W_prod, W_sc, W_ro_s, W_ro_v, eps, batch);
    gridbar();
    layer_phase<1>(smu, stage, W_mix, W_prod, W_sc, W_ro_s, W_ro_v, eps, batch);
    gridbar();

    // ======== P7: final output ========
    if (bid == 0 && tid < G_) {
        float nn = fmaxf((float)g_lcnt[tid], 1.0f);
        out[tid] = 0.5f * g_lacc[tid] / (nn * 13.0f);
    }
}

// ---------------- launcher ----------------
extern "C" void kernel_launch(void* const* d_in, const int* in_sizes, int n_in,
                              void* d_out, int out_size) {
    (void)in_sizes; (void)n_in; (void)out_size;
    k_mega<<<NBLK, NTHR>>>(
        (const float*)d_in[0],  (const float*)d_in[1],  (const float*)d_in[2],
        (const float*)d_in[3],  (const float*)d_in[4],  (const float*)d_in[5],
        (const float*)d_in[6],  (const float*)d_in[7],  (const float*)d_in[8],
        (const float*)d_in[9],  (const float*)d_in[10], (const float*)d_in[11],
        (const float*)d_in[12], (const int*)d_in[13],   (const int*)d_in[14],
        (const int*)d_in[15],   (float*)d_out);
}